// round 17
// baseline (speedup 1.0000x reference)
#include <cuda_runtime.h>
#include <math.h>

#define NIMG 8
#define AANCH 15
#define WW 100
#define HW 10000
#define HWA 150000
#define NF4 37500
#define PRE 2000
#define POST 1000
#define GCAND 8192
#define SCAND 4096
#define STATIC_KEY 0xBFD9999Au   /* fkey(1.7f): static logit prefilter */

// ---------------- device scratch (static, no runtime alloc) ----------------
__device__ __align__(16) float g_boxes[NIMG][2048][4];              // compacted valid boxes, score order
__device__ float g_scores[NIMG][2048];
__device__ int   g_cnt[NIMG];                                       // V = #valid per image
__device__ unsigned long long g_mask[NIMG][2048][32];               // suppression bitmask rows
__device__ unsigned int g_hist[NIMG][2048];                         // level-1 logit-key histogram (self-reset)
__device__ unsigned int g_pcnt[NIMG];                               // prefilter counters (self-reset)
__device__ unsigned long long g_pre[NIMG][GCAND];                   // prefilter list: xkey<<32 | ~refIdx

__constant__ float c_sizes[5]  = {32.f, 64.f, 128.f, 256.f, 512.f};
__constant__ float c_ratios[3] = {0.5f, 1.f, 2.f};

// monotone float<->uint key (larger float <-> larger key)
__device__ __forceinline__ unsigned int fkey(float f) {
    unsigned int u = __float_as_uint(f);
    return (u & 0x80000000u) ? ~u : (u | 0x80000000u);
}
__device__ __forceinline__ float funkey(unsigned int k) {
    unsigned int u = (k & 0x80000000u) ? (k ^ 0x80000000u) : ~k;
    return __uint_as_float(u);
}
__device__ __forceinline__ unsigned int refidx(int j) {             // input-layout j -> reference HWA index
    return (unsigned)((j % HW) * AANCH + j / HW);
}

// margin-guarded IoU>0.7 decision, bit-identical to reference div compare
__device__ __forceinline__ unsigned long long ioubit(const float4& bb, float ai,
                                                     const float4& cc, float aj) {
    float xx1 = fmaxf(bb.x, cc.x), yy1 = fmaxf(bb.y, cc.y);
    float xx2 = fminf(bb.z, cc.z), yy2 = fminf(bb.w, cc.w);
    float iw = fmaxf(__fsub_rn(xx2, xx1), 0.f);
    float ih = fmaxf(__fsub_rn(yy2, yy1), 0.f);
    float inter = __fmul_rn(iw, ih);
    float den = __fadd_rn(__fsub_rn(__fadd_rn(ai, aj), inter), 1e-6f);
    float thr = __fmul_rn(0.7f, den);
    bool sup;
    if (fabsf(__fsub_rn(inter, thr)) > 1e-4f * den)
        sup = inter > thr;                        // decision identical outside margin
    else
        sup = __fdiv_rn(inter, den) > 0.7f;       // exact fallback (rare)
    return sup ? 1ull : 0ull;
}

// ---- kernel 1: logit-key histogram + static prefilter append (one pass) ----
__global__ __launch_bounds__(256) void hist_kernel(const float* __restrict__ obj) {
    const int n = blockIdx.y;
    const int lane = threadIdx.x & 31;
    const float4* ob4 = (const float4*)(obj + (size_t)n * HWA);
    unsigned int key[4];
    #pragma unroll
    for (int it = 0; it < 4; it++) {
        int v = blockIdx.x * 1024 + it * 256 + threadIdx.x;
        bool inb = v < NF4;
        float4 xv = make_float4(0.f, 0.f, 0.f, 0.f);
        if (inb) xv = ob4[v];
        key[0] = fkey(xv.x); key[1] = fkey(xv.y); key[2] = fkey(xv.z); key[3] = fkey(xv.w);
        #pragma unroll
        for (int s = 0; s < 4; s++) {
            unsigned int b = inb ? (key[s] >> 21) : 0xFFFFFFFFu;
            unsigned int mk = __match_any_sync(0xFFFFFFFFu, b);
            if (b != 0xFFFFFFFFu && lane == (__ffs(mk) - 1))
                atomicAdd(&g_hist[n][b], (unsigned)__popc(mk));
        }
        int hm = 0;
        if (inb) {
            #pragma unroll
            for (int s = 0; s < 4; s++) hm |= (key[s] >= STATIC_KEY) << s;
        }
        if (__any_sync(0xFFFFFFFFu, hm)) {
            int cnt = __popc(hm);
            int pre = cnt;
            #pragma unroll
            for (int o = 1; o < 32; o <<= 1) {
                int t = __shfl_up_sync(0xFFFFFFFFu, pre, o);
                if (lane >= o) pre += t;
            }
            int total = __shfl_sync(0xFFFFFFFFu, pre, 31);
            unsigned int base = 0;
            if (lane == 31) base = atomicAdd(&g_pcnt[n], (unsigned)total);
            base = __shfl_sync(0xFFFFFFFFu, base, 31);
            unsigned int off = base + (unsigned)(pre - cnt);
            int r = 0;
            #pragma unroll
            for (int s = 0; s < 4; s++) {
                if (hm & (1 << s)) {
                    unsigned int p = off + r++;
                    if (p < GCAND) {
                        int j = (blockIdx.x * 1024 + it * 256 + threadIdx.x) * 4 + s;
                        g_pre[n][p] = ((unsigned long long)key[s] << 32)
                                    | (unsigned int)(~refidx(j));
                    }
                }
            }
        }
    }
}

// ---- kernel 2: pick + refine + sigmoid convert + sort + decode + compact ---
__global__ __launch_bounds__(1024) void sortdecode_kernel(const float* __restrict__ obj,
                                                          const float* __restrict__ deltas)
{
    const int n = blockIdx.x;
    const int tid = threadIdx.x;
    const float* ob = obj + (size_t)n * HWA;
    const float* dl = deltas + (size_t)n * HWA * 4;

    __shared__ unsigned int hist[2048];
    __shared__ unsigned long long cand[SCAND];
    __shared__ unsigned int s_b1, s_b2, s_nc2;

    // ---- pick: level-1 suffix scan over global histogram (+ self-reset) ----
    hist[tid] = g_hist[n][tid];
    hist[tid + 1024] = g_hist[n][tid + 1024];
    g_hist[n][tid] = 0;
    g_hist[n][tid + 1024] = 0;
    __syncthreads();
    for (int off = 1; off < 2048; off <<= 1) {
        unsigned a0 = hist[tid]        + ((tid + off < 2048)        ? hist[tid + off]        : 0u);
        unsigned a1 = hist[tid + 1024] + ((tid + 1024 + off < 2048) ? hist[tid + 1024 + off] : 0u);
        __syncthreads();
        hist[tid] = a0; hist[tid + 1024] = a1;
        __syncthreads();
    }
    #pragma unroll
    for (int q = 0; q < 2; q++) {
        int idx = tid + q * 1024;
        unsigned s = hist[idx];
        unsigned snx = (idx < 2047) ? hist[idx + 1] : 0u;
        if (s >= PRE && snx < PRE) s_b1 = (unsigned)idx;
    }
    __syncthreads();
    // margin (2^16 key ulps in logit space) >> sigmoid-tie plateau width
    const unsigned int T1 = (s_b1 >= 1u) ? ((s_b1 << 21) - 65536u) : 0u;

    unsigned int pcnt = g_pcnt[n];
    const bool fast = (T1 >= STATIC_KEY) && (pcnt <= GCAND);
    if (pcnt > GCAND) pcnt = GCAND;
    if (tid == 0) s_nc2 = 0;
    hist[tid] = 0; hist[tid + 1024] = 0;
    __syncthreads();

    // refine histogram over next 11 key bits (logit space; cap = everything above)
    if (fast) {
        for (unsigned int p = tid; p < pcnt; p += 1024) {
            unsigned int k = (unsigned int)(g_pre[n][p] >> 32);
            if (k >= T1) atomicAdd(&hist[min((k - T1) >> 10, 2047u)], 1u);
        }
    } else {
        for (int j = tid; j < HWA; j += 1024) {         // cold fallback: full rescan
            unsigned int k = fkey(ob[j]);
            if (k >= T1) atomicAdd(&hist[min((k - T1) >> 10, 2047u)], 1u);
        }
    }
    __syncthreads();
    for (int off = 1; off < 2048; off <<= 1) {
        unsigned a0 = hist[tid]        + ((tid + off < 2048)        ? hist[tid + off]        : 0u);
        unsigned a1 = hist[tid + 1024] + ((tid + 1024 + off < 2048) ? hist[tid + 1024 + off] : 0u);
        __syncthreads();
        hist[tid] = a0; hist[tid + 1024] = a1;
        __syncthreads();
    }
    #pragma unroll
    for (int q = 0; q < 2; q++) {
        int idx = tid + q * 1024;
        unsigned s = hist[idx];
        unsigned snx = (idx < 2047) ? hist[idx + 1] : 0u;
        if (s >= PRE && snx < PRE) s_b2 = (unsigned)idx;
    }
    __syncthreads();
    unsigned int B = T1 + (s_b2 << 10);
    const unsigned int Bm = (B >= 256u) ? (B - 256u) : 0u;   // tie-safety margin

    // gather superset, converting logit key -> exact sigmoid key (bit-match XLA)
    if (fast) {
        for (unsigned int p = tid; p < pcnt; p += 1024) {
            unsigned long long c = g_pre[n][p];
            unsigned int k = (unsigned int)(c >> 32);
            if (k >= Bm) {
                float x = funkey(k);
                float s = __fdiv_rn(1.0f, __fadd_rn(1.0f, expf(-x)));
                unsigned int q2 = atomicAdd(&s_nc2, 1u);
                if (q2 < SCAND)
                    cand[q2] = ((unsigned long long)fkey(s) << 32) | (unsigned int)c;
            }
        }
    } else {
        for (int j = tid; j < HWA; j += 1024) {
            float x = ob[j];
            unsigned int k = fkey(x);
            if (k >= Bm) {
                float s = __fdiv_rn(1.0f, __fadd_rn(1.0f, expf(-x)));
                unsigned int q2 = atomicAdd(&s_nc2, 1u);
                if (q2 < SCAND)
                    cand[q2] = ((unsigned long long)fkey(s) << 32) | (unsigned int)(~refidx(j));
            }
        }
    }
    __syncthreads();
    unsigned int nc2 = s_nc2; if (nc2 > SCAND) nc2 = SCAND;
    const int ssz = (nc2 <= 2048) ? 2048 : SCAND;           // usually 2048: cheaper sort
    for (unsigned int p = nc2 + tid; p < (unsigned)ssz; p += 1024) cand[p] = 0ull;
    __syncthreads();

    // bitonic sort, descending composite (sigmoid-bits desc, index asc)
    for (int len = 2; len <= ssz; len <<= 1) {
        for (int stride = len >> 1; stride > 0; stride >>= 1) {
            for (int v = tid; v < ssz / 2; v += 1024) {
                int low = v & (stride - 1);
                int pos = ((v ^ low) << 1) | low;
                int par = pos + stride;
                unsigned long long a = cand[pos], b = cand[par];
                bool desc = ((pos & len) == 0);
                if (desc ? (a < b) : (a > b)) { cand[pos] = b; cand[par] = a; }
            }
            __syncthreads();
        }
    }

    // decode top PRE, clip, min-size filter
    float bxv[2][4]; float scv[2]; unsigned validq[2];
    #pragma unroll
    for (int q = 0; q < 2; q++) {
        int r = tid + q * 1024;
        validq[q] = 0;
        if (r < PRE) {
            unsigned long long c = cand[r];
            unsigned int k = (unsigned int)(c >> 32);
            unsigned int i = ~((unsigned int)c);
            scv[q] = funkey(k);                        // exact sigmoid bits
            int a = (int)(i % AANCH);
            int cell = (int)(i / AANCH);
            int x = cell % WW, y = cell / WW;
            int rIdx = a / 5, sIdx = a % 5;
            float hr = sqrtf(c_ratios[rIdx]);
            float wr = __fdiv_rn(1.0f, hr);
            float wss = __fmul_rn(wr, c_sizes[sIdx]);
            float hss = __fmul_rn(hr, c_sizes[sIdx]);
            float bx1 = rintf(-0.5f * wss), bx2 = rintf(0.5f * wss);
            float by1 = rintf(-0.5f * hss), by2 = rintf(0.5f * hss);
            float ax1 = x * 16.f + bx1, ax2 = x * 16.f + bx2;
            float ay1 = y * 16.f + by1, ay2 = y * 16.f + by2;
            float wa = ax2 - ax1, ha = ay2 - ay1;      // exact integers
            float cxa = ax1 + 0.5f * wa, cya = ay1 + 0.5f * ha;
            float ddx = dl[(a * 4 + 0) * HW + cell];
            float ddy = dl[(a * 4 + 1) * HW + cell];
            float ddw = fminf(dl[(a * 4 + 2) * HW + cell], 4.1351665567423563f);
            float ddh = fminf(dl[(a * 4 + 3) * HW + cell], 4.1351665567423563f);
            float cx = __fadd_rn(__fmul_rn(ddx, wa), cxa);
            float cy = __fadd_rn(__fmul_rn(ddy, ha), cya);
            float w  = __fmul_rn(expf(ddw), wa);
            float h  = __fmul_rn(expf(ddh), ha);
            float x1 = __fsub_rn(cx, __fmul_rn(0.5f, w));
            float y1 = __fsub_rn(cy, __fmul_rn(0.5f, h));
            float x2 = __fadd_rn(cx, __fmul_rn(0.5f, w));
            float y2 = __fadd_rn(cy, __fmul_rn(0.5f, h));
            x1 = fminf(fmaxf(x1, 0.f), 1600.f);
            y1 = fminf(fmaxf(y1, 0.f), 1600.f);
            x2 = fminf(fmaxf(x2, 0.f), 1600.f);
            y2 = fminf(fmaxf(y2, 0.f), 1600.f);
            bxv[q][0] = x1; bxv[q][1] = y1; bxv[q][2] = x2; bxv[q][3] = y2;
            validq[q] = (__fsub_rn(x2, x1) >= 1e-3f) && (__fsub_rn(y2, y1) >= 1e-3f);
        }
    }
    __syncthreads();
    // parallel prefix sum of valid flags
    hist[tid] = (tid < PRE) ? validq[0] : 0u;
    hist[tid + 1024] = (tid + 1024 < PRE) ? validq[1] : 0u;
    __syncthreads();
    for (int off = 1; off < 2048; off <<= 1) {
        unsigned a0 = hist[tid]        + ((tid >= off)        ? hist[tid - off]        : 0u);
        unsigned a1 = hist[tid + 1024] + ((tid + 1024 >= off) ? hist[tid + 1024 - off] : 0u);
        __syncthreads();
        hist[tid] = a0; hist[tid + 1024] = a1;
        __syncthreads();
    }
    if (tid == 0) { g_cnt[n] = (int)hist[PRE - 1]; g_pcnt[n] = 0; }   // + self-reset
    #pragma unroll
    for (int q = 0; q < 2; q++) {
        int r = tid + q * 1024;
        if (r < PRE && validq[q]) {
            int p = (int)hist[r] - 1;
            g_boxes[n][p][0] = bxv[q][0];
            g_boxes[n][p][1] = bxv[q][1];
            g_boxes[n][p][2] = bxv[q][2];
            g_boxes[n][p][3] = bxv[q][3];
            g_scores[n][p]   = scv[q];
        }
    }
}

// ---- kernel B: IoU bitmask, 2 rows/thread, branchless inner loop -----------
__global__ __launch_bounds__(128) void iou_kernel() {
    const int n = blockIdx.z, bi = blockIdx.y, bj = blockIdx.x;
    if (bi * 4 > bj) return;                            // whole 256-row stripe below diagonal
    const int V = g_cnt[n];
    __shared__ float4 cb[64];
    __shared__ float ca[64];
    const int j0 = bj * 64;
    const int t = threadIdx.x;
    if (t < 64) {
        int j = j0 + t;
        float4 b = make_float4(0.f, 0.f, 0.f, 0.f);
        if (j < V) b = *reinterpret_cast<const float4*>(g_boxes[n][j]);
        cb[t] = b;
        ca[t] = __fmul_rn(__fsub_rn(b.z, b.x), __fsub_rn(b.w, b.y));
    }
    __syncthreads();

    const int i0 = bi * 256 + t;
    const int i1 = i0 + 128;
    const int dlim = 64 * (bj + 1);
    const bool w0 = (i0 < dlim);
    const bool w1 = (i1 < dlim);
    if (!w0 && !w1) return;

    float4 bb0 = *reinterpret_cast<const float4*>(g_boxes[n][i0]);
    float4 bb1 = *reinterpret_cast<const float4*>(g_boxes[n][i1]);
    float ai0 = __fmul_rn(__fsub_rn(bb0.z, bb0.x), __fsub_rn(bb0.w, bb0.y));
    float ai1 = __fmul_rn(__fsub_rn(bb1.z, bb1.x), __fsub_rn(bb1.w, bb1.y));

    unsigned long long m0 = 0ull, m1 = 0ull;
    #pragma unroll 8
    for (int u = 0; u < 64; u++) {
        float4 cc = cb[u];
        float aj = ca[u];
        m0 |= ioubit(bb0, ai0, cc, aj) << u;
        m1 |= ioubit(bb1, ai1, cc, aj) << u;
    }

    int tm = V - j0;
    if (tm <= 0) { m0 = 0ull; m1 = 0ull; }
    else if (tm < 64) { unsigned long long hi = (1ull << tm) - 1ull; m0 &= hi; m1 &= hi; }
    int d0 = i0 - j0;
    if (d0 >= 0) m0 &= ~((2ull << d0) - 1ull);
    int d1 = i1 - j0;
    if (d1 >= 0) m1 &= ~((2ull << d1) - 1ull);

    if (w0) g_mask[n][i0][bj] = m0;
    if (w1) g_mask[n][i1][bj] = m1;
}

// ---- kernel C: pipelined greedy NMS ---------------------------------------
// One barrier per 64-row block. Warp 0 decides block w (serial); warps 1-7
// concurrently prefetch block w+1's needs: column-(w+1) OR-gather over rows
// < 64w (skeep words final), the 64 "fix" rows [64w,64w+64) of column w+1
// (keep-masked later), and the next diagonal. Double-buffered by parity:
// block w's data lives in buffer [w&1]; producers write [(w+1)&1].
__global__ __launch_bounds__(256) void nms_kernel(float* __restrict__ out) {
    const int n = blockIdx.x;
    const int tid = threadIdx.x;
    const int lane = tid & 31, wid = tid >> 5;
    const int V = g_cnt[n];
    const int nblk = (V + 63) >> 6;                    // <= 32

    __shared__ unsigned long long skeep[32];
    __shared__ unsigned long long sdiag[2][64];
    __shared__ unsigned long long sfix[2][64];
    __shared__ unsigned long long spart[2][8];
    __shared__ int spfx[33];
    __shared__ int s_kc;

    if (tid < 32) skeep[tid] = 0ull;
    if (tid == 0) s_kc = 0;
    if (tid < 64) sdiag[0][tid] = (tid < V) ? g_mask[n][tid][0] : 0ull;
    __syncthreads();

    for (int w = 0; w < nblk; w++) {
        if (s_kc >= POST) break;                       // prior-block count (post-barrier visible)
        const int p = w & 1, np = p ^ 1;
        const int base = w << 6;

        if (wid == 0) {
            // combine sup_w = (fix & keep_{w-1}) | spart[1..7]   (all parity p)
            unsigned long long sup = 0ull;
            if (w > 0) {
                unsigned long long kprev = skeep[w - 1];
                unsigned long long v =
                      (sfix[p][lane]      & (0ull - ((kprev >> lane) & 1ull)))
                    | (sfix[p][lane + 32] & (0ull - ((kprev >> (lane + 32)) & 1ull)));
                #pragma unroll
                for (int o = 16; o > 0; o >>= 1)
                    v |= __shfl_xor_sync(0xFFFFFFFFu, v, o);
                sup = v;
            }
            if (lane == 0) {
                if (w > 0) {
                    #pragma unroll
                    for (int q = 1; q < 8; q++) sup |= spart[p][q];
                }
                unsigned long long remw = sup, keep = 0ull;
                #pragma unroll
                for (int u = 0; u < 64; u++) {
                    unsigned long long bc =
                        (unsigned long long)(((long long)(remw << (63 - u))) >> 63);
                    keep |= ~bc & (1ull << u);
                    remw |= sdiag[p][u] & ~bc;
                }
                int lim = V - base;
                if (lim < 64) keep &= (1ull << lim) - 1ull;
                skeep[w] = keep;
                s_kc += __popcll(keep);
            }
        } else if (w + 1 < nblk) {
            const int nb = base + 64;
            // (a) gather column w+1 over rows < base (224 threads)
            unsigned long long part = 0ull;
            for (int r = tid - 32; r < base; r += 224) {
                unsigned long long km = skeep[r >> 6];
                part |= g_mask[n][r][w + 1] & (0ull - ((km >> (r & 63)) & 1ull));
            }
            #pragma unroll
            for (int o = 16; o > 0; o >>= 1)
                part |= __shfl_xor_sync(0xFFFFFFFFu, part, o);
            if (lane == 0) spart[np][wid] = part;
            // (b) fix rows [base, base+64), column w+1
            if (tid >= 32 && tid < 96) {
                int row = base + (tid - 32);
                sfix[np][tid - 32] = (row < V) ? g_mask[n][row][w + 1] : 0ull;
            }
            // (c) diagonal for block w+1
            if (tid >= 96 && tid < 160) {
                int row = nb + (tid - 96);
                sdiag[np][tid - 96] = (row < V) ? g_mask[n][row][w + 1] : 0ull;
            }
        }
        __syncthreads();
    }

    if (tid == 0) {
        int c = 0;
        #pragma unroll
        for (int q = 0; q < 32; q++) { spfx[q] = c; c += __popcll(skeep[q]); }
        spfx[32] = c;
    }
    __syncthreads();

    float* po = out + (size_t)n * POST * 5;
    const int oc = min(spfx[32], POST);
    for (int i = tid; i < V; i += 256) {
        unsigned long long km = skeep[i >> 6];
        if ((km >> (i & 63)) & 1ull) {
            int rank = spfx[i >> 6] + __popcll(km & ((1ull << (i & 63)) - 1ull));
            if (rank < POST) {
                float4 b = *reinterpret_cast<const float4*>(g_boxes[n][i]);
                po[rank * 5 + 0] = b.x;
                po[rank * 5 + 1] = b.y;
                po[rank * 5 + 2] = b.z;
                po[rank * 5 + 3] = b.w;
                po[rank * 5 + 4] = g_scores[n][i];
            }
        }
    }
    for (int t = oc * 5 + tid; t < POST * 5; t += 256) po[t] = 0.f;
}

// ---------------- launch ----------------------------------------------------
extern "C" void kernel_launch(void* const* d_in, const int* in_sizes, int n_in,
                              void* d_out, int out_size) {
    const float* obj = (const float*)d_in[0];
    const float* dl  = (const float*)d_in[1];
    if (in_sizes[0] != NIMG * HWA) { const float* t = obj; obj = dl; dl = t; }

    dim3 gh(37, NIMG);
    hist_kernel<<<gh, 256>>>(obj);
    sortdecode_kernel<<<NIMG, 1024>>>(obj, dl);
    dim3 gb(32, 8, NIMG);
    iou_kernel<<<gb, 128>>>();
    nms_kernel<<<NIMG, 256>>>((float*)d_out);
}